// round 7
// baseline (speedup 1.0000x reference)
#include <cuda_runtime.h>
#include <cuda_bf16.h>
#include <cuda_fp16.h>
#include <math.h>
#include <stdint.h>

#define IN_DIM 256
#define OUT_DIM 256
#define DK 32
#define MAXN 50000
#define MAXE 800000

// ---------------- static device scratch (no cudaMalloc anywhere) ------------
__device__ __nv_bfloat16 g_AGh[MAXN * OUT_DIM];
__device__ __nv_bfloat16 g_AGl[MAXN * OUT_DIM];
__device__ __nv_bfloat16 g_Wh [4 * OUT_DIM * IN_DIM];
__device__ __nv_bfloat16 g_Wl [4 * OUT_DIM * IN_DIM];
__device__ __half g_Qh [MAXN * OUT_DIM];
__device__ __half g_Krh[MAXN * OUT_DIM];
__device__ __half g_Vh [MAXN * OUT_DIM];
__device__ int   g_deg[MAXN];
__device__ int   g_ptr[MAXN + 1];
__device__ int   g_cur[MAXN];
__device__ int   g_src[MAXE];
__device__ int   g_bsum[128];

// ---------------- asm helpers (family-common: sm_80+) -------------------------
__device__ __forceinline__ uint32_t smem_u32(const void* p) {
    uint32_t a;
    asm("{ .reg .u64 t; cvta.to.shared.u64 t, %1; cvt.u32.u64 %0, t; }"
        : "=r"(a) : "l"(p));
    return a;
}
__device__ __forceinline__ void cp16(uint32_t dst, const void* src, uint32_t bytes) {
    asm volatile("cp.async.cg.shared.global [%0], [%1], 16, %2;"
                 :: "r"(dst), "l"(src), "r"(bytes));
}
#define CP_COMMIT() asm volatile("cp.async.commit_group;" ::: "memory")
#define CP_WAIT(n)  asm volatile("cp.async.wait_group %0;" :: "n"(n) : "memory")

__device__ __forceinline__ void ldm_x4(uint32_t* r, uint32_t addr) {
    asm volatile("ldmatrix.sync.aligned.m8n8.x4.shared.b16 {%0,%1,%2,%3}, [%4];"
                 : "=r"(r[0]), "=r"(r[1]), "=r"(r[2]), "=r"(r[3]) : "r"(addr));
}
__device__ __forceinline__ void ldm_x2(uint32_t* r, uint32_t addr) {
    asm volatile("ldmatrix.sync.aligned.m8n8.x2.shared.b16 {%0,%1}, [%2];"
                 : "=r"(r[0]), "=r"(r[1]) : "r"(addr));
}
__device__ __forceinline__ void mma_bf16(float* c, const uint32_t* a, const uint32_t* b) {
    asm volatile("mma.sync.aligned.m16n8k16.row.col.f32.bf16.bf16.f32 "
                 "{%0,%1,%2,%3}, {%4,%5,%6,%7}, {%8,%9}, {%0,%1,%2,%3};"
                 : "+f"(c[0]), "+f"(c[1]), "+f"(c[2]), "+f"(c[3])
                 : "r"(a[0]), "r"(a[1]), "r"(a[2]), "r"(a[3]), "r"(b[0]), "r"(b[1]));
}

// ---------------- split helpers -----------------------------------------------
__device__ __forceinline__ void split2(float x, float y,
                                       __nv_bfloat162& hi, __nv_bfloat162& lo) {
    __nv_bfloat16 hx = __float2bfloat16(x), hy = __float2bfloat16(y);
    __nv_bfloat16 lx = __float2bfloat16(x - __bfloat162float(hx));
    __nv_bfloat16 ly = __float2bfloat16(y - __bfloat162float(hy));
    hi = __nv_bfloat162(hx, hy);
    lo = __nv_bfloat162(lx, ly);
}
// all 4 weight matrices in one launch
__global__ void cvt_split_w4_kernel(const float4* __restrict__ W0,
                                    const float4* __restrict__ W1,
                                    const float4* __restrict__ W2,
                                    const float4* __restrict__ W3) {
    __nv_bfloat162* hi = reinterpret_cast<__nv_bfloat162*>(g_Wh);
    __nv_bfloat162* lo = reinterpret_cast<__nv_bfloat162*>(g_Wl);
    const float4* Ws[4] = {W0, W1, W2, W3};
    for (int i = blockIdx.x * blockDim.x + threadIdx.x; i < 65536;
         i += gridDim.x * blockDim.x) {
        float4 v = Ws[i >> 14][i & 16383];
        split2(v.x, v.y, hi[2 * i],     lo[2 * i]);
        split2(v.z, v.w, hi[2 * i + 1], lo[2 * i + 1]);
    }
}

// ---------------- CSR build ----------------------------------------------------
__global__ void count_kernel(const int* __restrict__ col, int E) {
    for (int e = blockIdx.x * blockDim.x + threadIdx.x; e < E;
         e += gridDim.x * blockDim.x)
        atomicAdd(&g_deg[col[e]], 1);
}
__global__ void scan_partial_kernel(int n) {
    __shared__ int sh[1024];
    int i = blockIdx.x * 1024 + threadIdx.x;
    int v = (i < n) ? g_deg[i] : 0;
    sh[threadIdx.x] = v;
    __syncthreads();
    for (int off = 1; off < 1024; off <<= 1) {
        int t = (threadIdx.x >= off) ? sh[threadIdx.x - off] : 0;
        __syncthreads();
        sh[threadIdx.x] += t;
        __syncthreads();
    }
    if (i < n) g_ptr[i] = sh[threadIdx.x] - v;
    if (threadIdx.x == 1023) g_bsum[blockIdx.x] = sh[1023];
}
__global__ void scan_bsums_kernel(int nb) {
    if (threadIdx.x == 0) {
        int s = 0;
        for (int b = 0; b < nb; b++) { int t = g_bsum[b]; g_bsum[b] = s; s += t; }
    }
}
__global__ void scan_add_kernel(int n, int E) {
    int i = blockIdx.x * blockDim.x + threadIdx.x;
    if (i < n) {
        int p = g_ptr[i] + g_bsum[i >> 10];
        g_ptr[i] = p;
        g_cur[i] = p;
    }
    if (i == 0) g_ptr[n] = E;
}
__global__ void scatter_kernel(const int* __restrict__ row,
                               const int* __restrict__ col, int E) {
    for (int e = blockIdx.x * blockDim.x + threadIdx.x; e < E;
         e += gridDim.x * blockDim.x) {
        int pos = atomicAdd(&g_cur[col[e]], 1);
        g_src[pos] = row[e];
    }
}

// ---------------- fused-convert 3M-split HMMA GEMM ----------------------------
// C[M,256] = A[M,256] @ W^T + bias(+bias2).  CTA tile 128x256 (full N), 512 thr.
// K=256 as 4 physical k-tiles of 64; each tile runs 3 passes:
//   Ah*Wh + Ah*Wl + Al*Wh  (same accumulator).
// A source: either fp32 (user/item concat, split on the fly) or bf16 pre-split.
// smem per stage 96KB: Ah(16K) Al(16K) Wh(32K) Wl(32K); 2 stages.
#define S_AH 0
#define S_AL 16384
#define S_WH 32768
#define S_WL 65536
#define STG  98304
#define GEMM_SMEM (2 * STG)

__global__ void __launch_bounds__(512, 1)
gemm_fused_kernel(const float* __restrict__ Au, const float* __restrict__ Ai, int NU,
                  const __nv_bfloat16* __restrict__ Ahp, const __nv_bfloat16* __restrict__ Alp,
                  const __nv_bfloat16* __restrict__ Wh, const __nv_bfloat16* __restrict__ Wl,
                  const float* __restrict__ bias, const float* __restrict__ bias2,
                  float* __restrict__ C, __half* __restrict__ Ch, int M) {
    extern __shared__ char smem[];
    const uint32_t sb = smem_u32(smem);
    const int tid = threadIdx.x, wid = tid >> 5, lid = tid & 31;
    const int bm = blockIdx.x * 128;
    const int wr = wid & 3;       // warp row: 4 x 32
    const int wc = wid >> 2;      // warp col: 4 x 64
    const bool f32path = (Au != nullptr);

    float acc[2][8][4];
#pragma unroll
    for (int i = 0; i < 2; i++)
#pragma unroll
        for (int j = 0; j < 8; j++)
#pragma unroll
            for (int k = 0; k < 4; k++) acc[i][j][k] = 0.f;

    // ---- loaders ----
    auto cpW = [&](int kt, uint32_t stg) {
#pragma unroll
        for (int j = 0; j < 4; j++) {
            int idx = tid + j * 512;
            int r = idx >> 3, c = idx & 7;
            uint32_t sw = (uint32_t)r * 128 + (((uint32_t)(c ^ (r & 7))) << 4);
            cp16(sb + stg + S_WH + sw,
                 (const char*)Wh + (size_t)r * 512 + kt * 128 + c * 16, 16u);
            cp16(sb + stg + S_WL + sw,
                 (const char*)Wl + (size_t)r * 512 + kt * 128 + c * 16, 16u);
        }
    };
    auto cpA_bf16 = [&](int kt, uint32_t stg) {
#pragma unroll
        for (int j = 0; j < 2; j++) {
            int idx = tid + j * 512;
            int r = idx >> 3, c = idx & 7;
            int grow = bm + r;
            uint32_t bytes = (grow < M) ? 16u : 0u;
            uint32_t sw = (uint32_t)r * 128 + (((uint32_t)(c ^ (r & 7))) << 4);
            cp16(sb + stg + S_AH + sw,
                 (const char*)Ahp + (size_t)grow * 512 + kt * 128 + c * 16, bytes);
            cp16(sb + stg + S_AL + sw,
                 (const char*)Alp + (size_t)grow * 512 + kt * 128 + c * 16, bytes);
        }
    };
    float4 av[4];
    auto ldA_f32 = [&](int kt) {
#pragma unroll
        for (int j = 0; j < 4; j++) {
            int idx = tid + j * 512;
            int r = idx >> 4, c4 = idx & 15;
            int grow = bm + r;
            if (grow < M) {
                const float* src = (grow < NU) ? (Au + (size_t)grow * 256)
                                               : (Ai + (size_t)(grow - NU) * 256);
                av[j] = *(const float4*)(src + kt * 64 + c4 * 4);
            } else {
                av[j] = make_float4(0.f, 0.f, 0.f, 0.f);
            }
        }
    };
    auto stA_f32 = [&](uint32_t stg) {
#pragma unroll
        for (int j = 0; j < 4; j++) {
            int idx = tid + j * 512;
            int r = idx >> 4, c4 = idx & 15;
            __nv_bfloat162 h0, l0, h1, l1;
            split2(av[j].x, av[j].y, h0, l0);
            split2(av[j].z, av[j].w, h1, l1);
            int ch = c4 >> 1, half8 = (c4 & 1) * 8;
            uint32_t sw = (uint32_t)r * 128 + (((uint32_t)(ch ^ (r & 7))) << 4) + half8;
            uint2 hv, lv;
            hv.x = *(uint32_t*)&h0; hv.y = *(uint32_t*)&h1;
            lv.x = *(uint32_t*)&l0; lv.y = *(uint32_t*)&l1;
            *(uint2*)(smem + stg + S_AH + sw) = hv;
            *(uint2*)(smem + stg + S_AL + sw) = lv;
        }
    };
    auto compute = [&](uint32_t stg) {
#pragma unroll
        for (int p = 0; p < 3; p++) {
            const uint32_t aoff = sb + stg + ((p == 2) ? S_AL : S_AH);
            const uint32_t woff = sb + stg + ((p == 1) ? S_WL : S_WH);
#pragma unroll
            for (int ks = 0; ks < 4; ks++) {
                uint32_t a[2][4], b[8][2];
#pragma unroll
                for (int ma = 0; ma < 2; ma++) {
                    int ar = wr * 32 + ma * 16 + (lid & 15);
                    int ch = ks * 2 + (lid >> 4);
                    ldm_x4(a[ma], aoff + ar * 128 + ((ch ^ (ar & 7)) << 4));
                }
#pragma unroll
                for (int na = 0; na < 8; na++) {
                    int nr = wc * 64 + na * 8 + (lid & 7);
                    int ch = ks * 2 + ((lid >> 3) & 1);
                    ldm_x2(b[na], woff + nr * 128 + ((ch ^ (nr & 7)) << 4));
                }
#pragma unroll
                for (int ma = 0; ma < 2; ma++)
#pragma unroll
                    for (int na = 0; na < 8; na++)
                        mma_bf16(acc[ma][na], a[ma], b[na]);
            }
        }
    };

    // ---- prologue: tile 0 -> stage 0 ----
    if (f32path) { ldA_f32(0); stA_f32(0); }
    else cpA_bf16(0, 0);
    cpW(0, 0);
    CP_COMMIT(); CP_WAIT(0);
    __syncthreads();

    // ---- main loop ----
#pragma unroll
    for (int kt = 0; kt < 4; kt++) {
        const uint32_t st  = (kt & 1) * STG;
        const uint32_t nst = ((kt + 1) & 1) * STG;
        const bool pf = (kt < 3);
        if (pf) {
            if (f32path) ldA_f32(kt + 1);     // LDG issued, latency hidden by MMA
            else cpA_bf16(kt + 1, nst);
            cpW(kt + 1, nst);
            CP_COMMIT();
        }
        compute(st);
        if (pf) {
            if (f32path) stA_f32(nst);
            CP_WAIT(0);
        }
        __syncthreads();
    }

    // ---- epilogue ----
    const int g = lid >> 2;
    const int tg = (lid & 3) * 2;
#pragma unroll
    for (int ma = 0; ma < 2; ma++) {
        int mr = bm + wr * 32 + ma * 16 + g;
#pragma unroll
        for (int na = 0; na < 8; na++) {
            int nc = wc * 64 + na * 8 + tg;
            float b0 = bias[nc], b1 = bias[nc + 1];
            if (bias2) { b0 += bias2[nc]; b1 += bias2[nc + 1]; }
            float o00 = acc[ma][na][0] + b0, o01 = acc[ma][na][1] + b1;
            float o10 = acc[ma][na][2] + b0, o11 = acc[ma][na][3] + b1;
            if (Ch) {
                if (mr < M)
                    *(__half2*)(Ch + (size_t)mr * OUT_DIM + nc) = __floats2half2_rn(o00, o01);
                if (mr + 8 < M)
                    *(__half2*)(Ch + (size_t)(mr + 8) * OUT_DIM + nc) = __floats2half2_rn(o10, o11);
            } else {
                if (mr < M)
                    *(float2*)(C + (size_t)mr * OUT_DIM + nc) = make_float2(o00, o01);
                if (mr + 8 < M)
                    *(float2*)(C + (size_t)(mr + 8) * OUT_DIM + nc) = make_float2(o10, o11);
            }
        }
    }
}

// ---------------- per-node attention, fp16 gathers, bf16-split output ---------
__global__ void __launch_bounds__(128)
attn_kernel(int N) {
    const int n = blockIdx.x;
    if (n >= N) return;
    const int tid = threadIdx.x;
    const int w = tid >> 5, lid = tid & 31;
    const int head = w * 2 + (lid >> 4);
    const int sl = lid & 15;
    const int h2off = head * 16 + sl;
    const int beg = g_ptr[n];
    const int end = g_ptr[n + 1];

    const __half2* Qh2  = reinterpret_cast<const __half2*>(g_Qh);
    const __half2* Krh2 = reinterpret_cast<const __half2*>(g_Krh);
    const __half2* Vh2  = reinterpret_cast<const __half2*>(g_Vh);

    const float2 qf = __half22float2(Qh2[(size_t)n * 128 + h2off]);
    const float inv_sqrt_dk = 0.17677669529663689f;

    float m = -INFINITY, s = 0.f;
    float ax = 0.f, ay = 0.f;

    for (int i = beg; i < end; i++) {
        int r = g_src[i];
        float2 kf = __half22float2(Krh2[(size_t)r * 128 + h2off]);
        float2 vf = __half22float2(Vh2[(size_t)r * 128 + h2off]);
        float p = qf.x * kf.x + qf.y * kf.y;
        p += __shfl_xor_sync(0xffffffffu, p, 8);
        p += __shfl_xor_sync(0xffffffffu, p, 4);
        p += __shfl_xor_sync(0xffffffffu, p, 2);
        p += __shfl_xor_sync(0xffffffffu, p, 1);
        float xsc = p * inv_sqrt_dk;
        float nm = fmaxf(m, xsc);
        float scale = __expf(m - nm);
        float ex = __expf(xsc - nm);
        s = s * scale + ex;
        ax = ax * scale + ex * vf.x;
        ay = ay * scale + ex * vf.y;
        m = nm;
    }

    float ox = 0.f, oy = 0.f;
    if (s > 0.f) { float inv = 1.f / s; ox = ax * inv; oy = ay * inv; }
    __nv_bfloat162 hi, lo;
    split2(ox, oy, hi, lo);
    reinterpret_cast<__nv_bfloat162*>(g_AGh)[(size_t)n * 128 + h2off] = hi;
    reinterpret_cast<__nv_bfloat162*>(g_AGl)[(size_t)n * 128 + h2off] = lo;
}

// ---------------- launch --------------------------------------------------------
extern "C" void kernel_launch(void* const* d_in, const int* in_sizes, int n_in,
                              void* d_out, int out_size) {
    const float* x    = (const float*)d_in[0];
    const int*   row  = (const int*)  d_in[1];
    const int*   col  = (const int*)  d_in[2];
    const float* rel  = (const float*)d_in[3];
    const float* user = (const float*)d_in[4];
    const float* item = (const float*)d_in[5];
    const float* Wq   = (const float*)d_in[6];
    const float* bq   = (const float*)d_in[7];
    const float* Wk   = (const float*)d_in[8];
    const float* bk   = (const float*)d_in[9];
    const float* Wv   = (const float*)d_in[10];
    const float* bv   = (const float*)d_in[11];
    const float* Wo   = (const float*)d_in[12];
    const float* bo   = (const float*)d_in[13];
    float* out = (float*)d_out;

    const int N  = in_sizes[0] / IN_DIM;
    const int E  = in_sizes[1];
    const int NU = in_sizes[4] / IN_DIM;

    __half *dQh, *dKrh, *dVh;
    __nv_bfloat16 *dAGh, *dAGl, *dWh, *dWl;
    int* dDeg;
    cudaGetSymbolAddress((void**)&dQh,  g_Qh);
    cudaGetSymbolAddress((void**)&dKrh, g_Krh);
    cudaGetSymbolAddress((void**)&dVh,  g_Vh);
    cudaGetSymbolAddress((void**)&dAGh, g_AGh);
    cudaGetSymbolAddress((void**)&dAGl, g_AGl);
    cudaGetSymbolAddress((void**)&dWh,  g_Wh);
    cudaGetSymbolAddress((void**)&dWl,  g_Wl);
    cudaGetSymbolAddress((void**)&dDeg, g_deg);

    cudaFuncSetAttribute(gemm_fused_kernel,
                         cudaFuncAttributeMaxDynamicSharedMemorySize, GEMM_SMEM);

    // 1. split weights (one launch)
    cvt_split_w4_kernel<<<256, 256>>>((const float4*)Wq, (const float4*)Wk,
                                      (const float4*)Wv, (const float4*)Wo);

    // 2. CSR build by destination (col)
    cudaMemsetAsync(dDeg, 0, (size_t)N * sizeof(int), 0);
    count_kernel<<<(E + 255) / 256, 256>>>(col, E);
    int nb = (N + 1023) / 1024;
    scan_partial_kernel<<<nb, 1024>>>(N);
    scan_bsums_kernel<<<1, 32>>>(nb);
    scan_add_kernel<<<(N + 255) / 256, 256>>>(N, E);
    scatter_kernel<<<(E + 255) / 256, 256>>>(row, col, E);

    // 3. projections (fused fp32->split-bf16 GEMM) -> fp16 intermediates
    int gx = (N + 127) / 128;
    gemm_fused_kernel<<<gx, 512, GEMM_SMEM>>>(user, item, NU, nullptr, nullptr,
                                              dWh + 0 * 65536, dWl + 0 * 65536,
                                              bq, nullptr, nullptr, dQh, N);
    gemm_fused_kernel<<<gx, 512, GEMM_SMEM>>>(user, item, NU, nullptr, nullptr,
                                              dWh + 1 * 65536, dWl + 1 * 65536,
                                              bk, rel, nullptr, dKrh, N);
    gemm_fused_kernel<<<gx, 512, GEMM_SMEM>>>(x, x, N, nullptr, nullptr,
                                              dWh + 2 * 65536, dWl + 2 * 65536,
                                              bv, nullptr, nullptr, dVh, N);

    // 4. attention (fp16 gathers, writes bf16 hi/lo split directly)
    attn_kernel<<<N, 128>>>(N);

    // 5. output projection (bf16 pre-split A) -> fp32 out
    gemm_fused_kernel<<<gx, 512, GEMM_SMEM>>>(nullptr, nullptr, 0, dAGh, dAGl,
                                              dWh + 3 * 65536, dWl + 3 * 65536,
                                              bo, nullptr, out, nullptr, N);
}